// round 1
// baseline (speedup 1.0000x reference)
#include <cuda_runtime.h>
#include <cuda_bf16.h>

// ---------------- problem constants ----------------
#define N_NODES 20000
#define N_EDGES 160000
// S = 8 edge features everywhere.

// ---------------- device scratch (static; no allocs) ----------------
__device__ float g_P[N_NODES * 320];      // P[n, s, o] for current layer (max 8*40)
__device__ float g_R[N_NODES * 40];       // R[n, o]
__device__ float g_AGG1[N_NODES * 40];    // layer1 pre-relu output accumulator
__device__ float g_AGG2[N_NODES * 24];
__device__ float g_AGG3[N_NODES * 24];
__device__ int   g_deg[N_NODES];
__device__ int   g_rowstart[N_NODES];
__device__ int   g_cursor[N_NODES];
__device__ int   g_tgtperm[N_EDGES];
__device__ float4 g_eperm[N_EDGES * 2];   // 8 floats per edge, src-sorted
__device__ float g_pool[24];

// ---------------- CSR build ----------------
__global__ void k_zero() {
    int i = blockIdx.x * blockDim.x + threadIdx.x;
    if (i < N_NODES) g_deg[i] = 0;
    if (i < 24) g_pool[i] = 0.0f;
}

__global__ void k_hist(const int2* __restrict__ ei) {
    int i = blockIdx.x * blockDim.x + threadIdx.x;
    if (i < N_EDGES) atomicAdd(&g_deg[ei[i].x], 1);
}

__global__ void k_scan() {
    __shared__ int ps[1024];
    int t = threadIdx.x;
    const int per = (N_NODES + 1023) / 1024;  // 20
    int base = t * per;
    int s = 0;
#pragma unroll
    for (int i = 0; i < per; i++) {
        int idx = base + i;
        if (idx < N_NODES) s += g_deg[idx];
    }
    ps[t] = s;
    __syncthreads();
    for (int off = 1; off < 1024; off <<= 1) {
        int v = ps[t];
        int add = (t >= off) ? ps[t - off] : 0;
        __syncthreads();
        ps[t] = v + add;
        __syncthreads();
    }
    int run = (t == 0) ? 0 : ps[t - 1];
#pragma unroll
    for (int i = 0; i < per; i++) {
        int idx = base + i;
        if (idx < N_NODES) {
            g_rowstart[idx] = run;
            g_cursor[idx] = run;
            run += g_deg[idx];
        }
    }
}

__global__ void k_scatter(const int2* __restrict__ ei, const float4* __restrict__ e) {
    int i = blockIdx.x * blockDim.x + threadIdx.x;
    if (i < N_EDGES) {
        int2 st = ei[i];
        int pos = atomicAdd(&g_cursor[st.x], 1);
        g_tgtperm[pos] = st.y;
        g_eperm[2 * pos] = e[2 * i];
        g_eperm[2 * pos + 1] = e[2 * i + 1];
    }
}

// ---------------- node kernel ----------------
// Computes, for each node n:
//   P[n, s, o] = sum_f h[n,f] * We[s, f*FO + o]            (cols 0 .. 8*FO)
//   R[n, o]    = sum_f h[n,f] * be[f*FO + o]               (cols 8*FO .. 9*FO)
//   AGG[n, o]  = sum_f h[n,f] * root[f*FO + o] + b[o]      (cols 9*FO .. 10*FO)
// h = x (layer 1) or relu(AGG_prev).
template <int LAYER, int FI, int FO>
__global__ __launch_bounds__(256) void k_node(
    const float* __restrict__ xin,
    const float* __restrict__ We, const float* __restrict__ be,
    const float* __restrict__ root, const float* __restrict__ bias)
{
    constexpr int COLS = 10 * FO;
    __shared__ float Wsh[FI * COLS];
    __shared__ float bsh[FO];
    int t = threadIdx.x;

    for (int idx = t; idx < FI * COLS; idx += 256) {
        int f = idx / COLS, c = idx % COLS;
        float w;
        if (c < 8 * FO) {
            int s = c / FO, o = c % FO;
            w = We[s * (FI * FO) + f * FO + o];
        } else if (c < 9 * FO) {
            int o = c - 8 * FO;
            w = be[f * FO + o];
        } else {
            int o = c - 9 * FO;
            w = root[f * FO + o];
        }
        Wsh[idx] = w;
    }
    for (int idx = t; idx < FO; idx += 256) bsh[idx] = bias[idx];
    __syncthreads();

    int node = blockIdx.x * 256 + t;
    if (node >= N_NODES) return;

    const float* hin;
    if (LAYER == 1)      hin = xin;
    else if (LAYER == 2) hin = g_AGG1;
    else                 hin = g_AGG2;
    float* AGG;
    if (LAYER == 1)      AGG = g_AGG1;
    else if (LAYER == 2) AGG = g_AGG2;
    else                 AGG = g_AGG3;

    float h[FI];
    const float4* hv = reinterpret_cast<const float4*>(hin + (size_t)node * FI);
#pragma unroll
    for (int f4 = 0; f4 < FI / 4; f4++) {
        float4 v = hv[f4];
        if (LAYER != 1) {
            v.x = fmaxf(v.x, 0.0f); v.y = fmaxf(v.y, 0.0f);
            v.z = fmaxf(v.z, 0.0f); v.w = fmaxf(v.w, 0.0f);
        }
        h[4 * f4 + 0] = v.x; h[4 * f4 + 1] = v.y;
        h[4 * f4 + 2] = v.z; h[4 * f4 + 3] = v.w;
    }

    const float4* Wv = reinterpret_cast<const float4*>(Wsh);
    float4* Pv = reinterpret_cast<float4*>(g_P) + (size_t)node * (8 * FO / 4);
    float4* Rv = reinterpret_cast<float4*>(g_R) + (size_t)node * (FO / 4);
    float4* Av = reinterpret_cast<float4*>(AGG) + (size_t)node * (FO / 4);

    constexpr int NCG = COLS / 16;  // colgroups of 16 floats
    for (int cg = 0; cg < NCG; cg++) {
        float4 acc0 = make_float4(0, 0, 0, 0);
        float4 acc1 = make_float4(0, 0, 0, 0);
        float4 acc2 = make_float4(0, 0, 0, 0);
        float4 acc3 = make_float4(0, 0, 0, 0);
#pragma unroll
        for (int f = 0; f < FI; f++) {
            float hvv = h[f];
            const float4* wrow = Wv + f * (COLS / 4) + cg * 4;
            float4 w0 = wrow[0], w1 = wrow[1], w2 = wrow[2], w3 = wrow[3];
            acc0.x += hvv * w0.x; acc0.y += hvv * w0.y; acc0.z += hvv * w0.z; acc0.w += hvv * w0.w;
            acc1.x += hvv * w1.x; acc1.y += hvv * w1.y; acc1.z += hvv * w1.z; acc1.w += hvv * w1.w;
            acc2.x += hvv * w2.x; acc2.y += hvv * w2.y; acc2.z += hvv * w2.z; acc2.w += hvv * w2.w;
            acc3.x += hvv * w3.x; acc3.y += hvv * w3.y; acc3.z += hvv * w3.z; acc3.w += hvv * w3.w;
        }
        float4 accs[4] = {acc0, acc1, acc2, acc3};
#pragma unroll
        for (int q = 0; q < 4; q++) {
            int cb = cg * 16 + q * 4;
            if (cb < 8 * FO) {
                Pv[cb / 4] = accs[q];
            } else if (cb < 9 * FO) {
                Rv[(cb - 8 * FO) / 4] = accs[q];
            } else {
                int o = cb - 9 * FO;
                float4 a = accs[q];
                a.x += bsh[o]; a.y += bsh[o + 1]; a.z += bsh[o + 2]; a.w += bsh[o + 3];
                Av[o / 4] = a;
            }
        }
    }
}

// ---------------- edge kernel ----------------
// One warp per src node. P[src], R[src] staged in SMEM once, reused over
// all out-edges: msg[o] = R[src,o] + sum_s e[s]*P[src,s,o]; red.v4 -> AGG[tgt].
template <int LAYER, int FO>
__global__ __launch_bounds__(256) void k_edge()
{
    constexpr int FO4 = FO / 4;
    constexpr int PF4 = 8 * FO / 4;
    __shared__ float4 Psh[8][PF4];
    __shared__ float4 Rsh[8][FO4];

    int t = threadIdx.x;
    int w = t >> 5, lane = t & 31;
    int src = blockIdx.x * 8 + w;
    if (src >= N_NODES) return;

    float* AGG;
    if (LAYER == 1)      AGG = g_AGG1;
    else if (LAYER == 2) AGG = g_AGG2;
    else                 AGG = g_AGG3;

    const float4* Pg = reinterpret_cast<const float4*>(g_P) + (size_t)src * PF4;
    for (int i = lane; i < PF4; i += 32) Psh[w][i] = Pg[i];
    const float4* Rg = reinterpret_cast<const float4*>(g_R) + (size_t)src * FO4;
    if (lane < FO4) Rsh[w][lane] = Rg[lane];
    __syncwarp();

    int d = g_deg[src];
    int start = g_rowstart[src];
    int items = d * FO4;
    for (int it = lane; it < items; it += 32) {
        int j = it / FO4, c = it % FO4;
        int pos = start + j;
        int tg = g_tgtperm[pos];
        float4 ea = g_eperm[2 * pos];
        float4 eb = g_eperm[2 * pos + 1];
        float4 m = Rsh[w][c];
#define ACC_TERM(ES, SI) { float4 p = Psh[w][(SI) * FO4 + c]; \
        m.x += (ES) * p.x; m.y += (ES) * p.y; m.z += (ES) * p.z; m.w += (ES) * p.w; }
        ACC_TERM(ea.x, 0) ACC_TERM(ea.y, 1) ACC_TERM(ea.z, 2) ACC_TERM(ea.w, 3)
        ACC_TERM(eb.x, 4) ACC_TERM(eb.y, 5) ACC_TERM(eb.z, 6) ACC_TERM(eb.w, 7)
#undef ACC_TERM
        float* dst = AGG + (size_t)tg * FO + c * 4;
        asm volatile("red.global.add.v4.f32 [%0], {%1,%2,%3,%4};"
                     :: "l"(dst), "f"(m.x), "f"(m.y), "f"(m.z), "f"(m.w)
                     : "memory");
    }
}

// ---------------- pool: g[o] = sum_n relu(AGG3[n,o]) ----------------
__global__ void k_pool()  // 240 threads: t%24 = col, t/24 = row slot (10 per block)
{
    __shared__ float sacc[24];
    int t = threadIdx.x;
    if (t < 24) sacc[t] = 0.0f;
    __syncthreads();
    int c = t % 24;
    int r0 = t / 24;
    float local = 0.0f;
    for (int r = blockIdx.x * 10 + r0; r < N_NODES; r += gridDim.x * 10) {
        float v = g_AGG3[r * 24 + c];
        local += fmaxf(v, 0.0f);
    }
    atomicAdd(&sacc[c], local);
    __syncthreads();
    if (t < 24) atomicAdd(&g_pool[t], sacc[t]);
}

// ---------------- MLP (single block) ----------------
template <int FI, int FO>
__device__ __forceinline__ void mlp_layer(const float* __restrict__ in, float* __restrict__ outb,
                                          const float* __restrict__ W, const float* __restrict__ bias,
                                          int t)
{
    constexpr int NJ4 = FO / 4;
    if (t < NJ4) {
        float4 acc = make_float4(0, 0, 0, 0);
        const float4* Wv = reinterpret_cast<const float4*>(W);
#pragma unroll 4
        for (int i = 0; i < FI; i++) {
            float ai = in[i];
            float4 wv = Wv[i * NJ4 + t];
            acc.x += ai * wv.x; acc.y += ai * wv.y;
            acc.z += ai * wv.z; acc.w += ai * wv.w;
        }
        float4 bb = reinterpret_cast<const float4*>(bias)[t];
        acc.x = fmaxf(acc.x + bb.x, 0.0f);
        acc.y = fmaxf(acc.y + bb.y, 0.0f);
        acc.z = fmaxf(acc.z + bb.z, 0.0f);
        acc.w = fmaxf(acc.w + bb.w, 0.0f);
        outb[4 * t + 0] = acc.x; outb[4 * t + 1] = acc.y;
        outb[4 * t + 2] = acc.z; outb[4 * t + 3] = acc.w;
    }
}

__global__ void k_mlp(const float* __restrict__ W1, const float* __restrict__ b1,
                      const float* __restrict__ W2, const float* __restrict__ b2,
                      const float* __restrict__ W3, const float* __restrict__ b3,
                      const float* __restrict__ W4, const float* __restrict__ b4,
                      const float* __restrict__ W5, const float* __restrict__ b5,
                      const float* __restrict__ W6, const float* __restrict__ b6,
                      float* __restrict__ out)
{
    __shared__ float a[768];
    __shared__ float bb[768];
    __shared__ float red[64];
    int t = threadIdx.x;
    if (t < 24) a[t] = g_pool[t];
    __syncthreads();
    mlp_layer<24, 96>(a, bb, W1, b1, t);   __syncthreads();
    mlp_layer<96, 256>(bb, a, W2, b2, t);  __syncthreads();
    mlp_layer<256, 768>(a, bb, W3, b3, t); __syncthreads();
    mlp_layer<768, 512>(bb, a, W4, b4, t); __syncthreads();
    mlp_layer<512, 64>(a, bb, W5, b5, t);  __syncthreads();
    if (t < 64) red[t] = bb[t] * W6[t];
    __syncthreads();
    if (t == 0) {
        float s = 0.0f;
#pragma unroll
        for (int i = 0; i < 64; i++) s += red[i];
        out[0] = s + b6[0];
    }
}

// ---------------- launcher ----------------
extern "C" void kernel_launch(void* const* d_in, const int* in_sizes, int n_in,
                              void* d_out, int out_size)
{
    const float* x    = (const float*)d_in[0];
    const int*   ei   = (const int*)d_in[1];
    const float* e    = (const float*)d_in[2];
    const float* We1  = (const float*)d_in[3];
    const float* be1  = (const float*)d_in[4];
    const float* root1= (const float*)d_in[5];
    const float* b1   = (const float*)d_in[6];
    const float* We2  = (const float*)d_in[7];
    const float* be2  = (const float*)d_in[8];
    const float* root2= (const float*)d_in[9];
    const float* b2   = (const float*)d_in[10];
    const float* We3  = (const float*)d_in[11];
    const float* be3  = (const float*)d_in[12];
    const float* root3= (const float*)d_in[13];
    const float* b3   = (const float*)d_in[14];
    const float* Wd1  = (const float*)d_in[15];
    const float* bd1  = (const float*)d_in[16];
    const float* Wd2  = (const float*)d_in[17];
    const float* bd2  = (const float*)d_in[18];
    const float* Wd3  = (const float*)d_in[19];
    const float* bd3  = (const float*)d_in[20];
    const float* Wd4  = (const float*)d_in[21];
    const float* bd4  = (const float*)d_in[22];
    const float* Wd5  = (const float*)d_in[23];
    const float* bd5  = (const float*)d_in[24];
    const float* Wd6  = (const float*)d_in[25];
    const float* bd6  = (const float*)d_in[26];

    const int2* ei2 = (const int2*)ei;
    const float4* e4 = (const float4*)e;

    // CSR build (per launch; deterministic work)
    k_zero<<<(N_NODES + 255) / 256, 256>>>();
    k_hist<<<N_EDGES / 256, 256>>>(ei2);
    k_scan<<<1, 1024>>>();
    k_scatter<<<N_EDGES / 256, 256>>>(ei2, e4);

    const int node_grid = (N_NODES + 255) / 256;
    const int edge_grid = N_NODES / 8;

    // Layer 1: 16 -> 40
    k_node<1, 16, 40><<<node_grid, 256>>>(x, We1, be1, root1, b1);
    k_edge<1, 40><<<edge_grid, 256>>>();
    // Layer 2: 40 -> 24
    k_node<2, 40, 24><<<node_grid, 256>>>(nullptr, We2, be2, root2, b2);
    k_edge<2, 24><<<edge_grid, 256>>>();
    // Layer 3: 24 -> 24
    k_node<3, 24, 24><<<node_grid, 256>>>(nullptr, We3, be3, root3, b3);
    k_edge<3, 24><<<edge_grid, 256>>>();

    k_pool<<<84, 240>>>();
    k_mlp<<<1, 768>>>(Wd1, bd1, Wd2, bd2, Wd3, bd3, Wd4, bd4, Wd5, bd5, Wd6, bd6,
                      (float*)d_out);
}

// round 2
// speedup vs baseline: 1.1783x; 1.1783x over previous
#include <cuda_runtime.h>
#include <cuda_bf16.h>

// ---------------- problem constants ----------------
#define N_NODES 20000
#define N_EDGES 160000
// S = 8 edge features everywhere.

// ---------------- device scratch (static; no allocs) ----------------
__device__ __align__(16) float g_P[N_NODES * 320];   // P[n, s, o] (max 8*40 cols)
__device__ __align__(16) float g_R[N_NODES * 40];    // R[n, o]
__device__ __align__(16) float g_AGG1[N_NODES * 40];
__device__ __align__(16) float g_AGG2[N_NODES * 24];
__device__ __align__(16) float g_AGG3[N_NODES * 24];
__device__ int   g_deg[N_NODES];
__device__ int   g_cursor[N_NODES];
__device__ int4  g_srt[N_EDGES];          // (src, tgt, origEdgeIdx, 0) sorted by src
__device__ float g_poolpart[84 * 24];
__device__ __align__(16) float g_v1[256];
__device__ __align__(16) float g_v2[768];
__device__ __align__(16) float g_v3[512];

// ---------------- f32x2 helpers ----------------
__device__ __forceinline__ void ffma2(unsigned long long& d, unsigned long long a,
                                      unsigned long long b) {
    asm("fma.rn.f32x2 %0, %1, %2, %0;" : "+l"(d) : "l"(a), "l"(b));
}
__device__ __forceinline__ unsigned long long packf2(float x) {
    unsigned long long r;
    asm("mov.b64 %0, {%1, %1};" : "=l"(r) : "f"(x));
    return r;
}
__device__ __forceinline__ float2 unpackf2(unsigned long long v) {
    float2 f;
    asm("mov.b64 {%0, %1}, %2;" : "=f"(f.x), "=f"(f.y) : "l"(v));
    return f;
}

// ---------------- CSR build ----------------
__global__ void k_zero() {
    int i = blockIdx.x * blockDim.x + threadIdx.x;
    if (i < N_NODES) g_deg[i] = 0;
}

__global__ void k_hist(const int2* __restrict__ ei) {
    int i = blockIdx.x * blockDim.x + threadIdx.x;
    if (i < N_EDGES) atomicAdd(&g_deg[ei[i].x], 1);
}

__global__ void k_scan() {
    __shared__ int ps[1024];
    int t = threadIdx.x;
    const int per = (N_NODES + 1023) / 1024;  // 20
    int base = t * per;
    int s = 0;
#pragma unroll
    for (int i = 0; i < per; i++) {
        int idx = base + i;
        if (idx < N_NODES) s += g_deg[idx];
    }
    ps[t] = s;
    __syncthreads();
    for (int off = 1; off < 1024; off <<= 1) {
        int v = ps[t];
        int add = (t >= off) ? ps[t - off] : 0;
        __syncthreads();
        ps[t] = v + add;
        __syncthreads();
    }
    int run = (t == 0) ? 0 : ps[t - 1];
#pragma unroll
    for (int i = 0; i < per; i++) {
        int idx = base + i;
        if (idx < N_NODES) {
            g_cursor[idx] = run;
            run += g_deg[idx];
        }
    }
}

__global__ void k_scatter(const int2* __restrict__ ei) {
    int i = blockIdx.x * blockDim.x + threadIdx.x;
    if (i < N_EDGES) {
        int2 st = ei[i];
        int pos = atomicAdd(&g_cursor[st.x], 1);
        g_srt[pos] = make_int4(st.x, st.y, i, 0);
    }
}

// ---------------- node kernel ----------------
// Per node n (2 nodes per thread, f32x2 packed math):
//   cols [0, 8*FO):      P[n,s,o] = sum_f h[n,f] * We[s, f*FO+o]
//   cols [8*FO, 9*FO):   R[n,o]   = sum_f h[n,f] * be[f*FO+o]
//   cols [9*FO, 10*FO):  AGG[n,o] = sum_f h[n,f] * root[f*FO+o] + b[o]
// h = x (layer 1) or relu(AGG_prev).
template <int LAYER, int FI, int FO>
__global__ __launch_bounds__(128) void k_node(
    const float* __restrict__ xin,
    const float* __restrict__ We, const float* __restrict__ be,
    const float* __restrict__ root, const float* __restrict__ bias)
{
    constexpr int COLS = 10 * FO;
    __shared__ __align__(16) float Wsh[FI * COLS];
    __shared__ float bsh[FO];
    int t = threadIdx.x;

    for (int idx = t; idx < FI * COLS; idx += 128) {
        int f = idx / COLS, c = idx % COLS;
        float w;
        if (c < 8 * FO) {
            int s = c / FO, o = c % FO;
            w = We[s * (FI * FO) + f * FO + o];
        } else if (c < 9 * FO) {
            int o = c - 8 * FO;
            w = be[f * FO + o];
        } else {
            int o = c - 9 * FO;
            w = root[f * FO + o];
        }
        Wsh[idx] = w;
    }
    for (int idx = t; idx < FO; idx += 128) bsh[idx] = bias[idx];
    __syncthreads();

    int n0 = blockIdx.x * 256 + t;
    int n1 = n0 + 128;
    bool v0 = n0 < N_NODES, v1 = n1 < N_NODES;
    if (!v0) return;

    const float* hin;
    if (LAYER == 1)      hin = xin;
    else if (LAYER == 2) hin = g_AGG1;
    else                 hin = g_AGG2;
    float* AGG;
    if (LAYER == 1)      AGG = g_AGG1;
    else if (LAYER == 2) AGG = g_AGG2;
    else                 AGG = g_AGG3;

    float h0[FI], h1[FI];
#pragma unroll
    for (int f4 = 0; f4 < FI / 4; f4++) {
        float4 a = reinterpret_cast<const float4*>(hin + (size_t)n0 * FI)[f4];
        float4 b = v1 ? reinterpret_cast<const float4*>(hin + (size_t)n1 * FI)[f4]
                      : make_float4(0, 0, 0, 0);
        if (LAYER != 1) {
            a.x = fmaxf(a.x, 0.f); a.y = fmaxf(a.y, 0.f); a.z = fmaxf(a.z, 0.f); a.w = fmaxf(a.w, 0.f);
            b.x = fmaxf(b.x, 0.f); b.y = fmaxf(b.y, 0.f); b.z = fmaxf(b.z, 0.f); b.w = fmaxf(b.w, 0.f);
        }
        h0[4*f4+0]=a.x; h0[4*f4+1]=a.y; h0[4*f4+2]=a.z; h0[4*f4+3]=a.w;
        h1[4*f4+0]=b.x; h1[4*f4+1]=b.y; h1[4*f4+2]=b.z; h1[4*f4+3]=b.w;
    }

    const ulonglong2* Wv = reinterpret_cast<const ulonglong2*>(Wsh);  // 2 f32x2 per load
    float4* Pv0 = reinterpret_cast<float4*>(g_P) + (size_t)n0 * (8 * FO / 4);
    float4* Pv1 = reinterpret_cast<float4*>(g_P) + (size_t)n1 * (8 * FO / 4);
    float4* Rv0 = reinterpret_cast<float4*>(g_R) + (size_t)n0 * (FO / 4);
    float4* Rv1 = reinterpret_cast<float4*>(g_R) + (size_t)n1 * (FO / 4);
    float4* Av0 = reinterpret_cast<float4*>(AGG) + (size_t)n0 * (FO / 4);
    float4* Av1 = reinterpret_cast<float4*>(AGG) + (size_t)n1 * (FO / 4);

    constexpr int NCG = COLS / 16;
    for (int cg = 0; cg < NCG; cg++) {
        unsigned long long acc0[8], acc1[8];
#pragma unroll
        for (int k = 0; k < 8; k++) { acc0[k] = 0ull; acc1[k] = 0ull; }
#pragma unroll
        for (int f = 0; f < FI; f++) {
            // 16 cols = 8 f32x2 = 4 ulonglong2 (LDS.128)
            const ulonglong2* wrow = Wv + f * (COLS / 4) + cg * 4;
            ulonglong2 wA = wrow[0], wB = wrow[1], wC = wrow[2], wD = wrow[3];
            unsigned long long ha = packf2(h0[f]);
            unsigned long long hb = packf2(h1[f]);
            ffma2(acc0[0], ha, wA.x); ffma2(acc0[1], ha, wA.y);
            ffma2(acc0[2], ha, wB.x); ffma2(acc0[3], ha, wB.y);
            ffma2(acc0[4], ha, wC.x); ffma2(acc0[5], ha, wC.y);
            ffma2(acc0[6], ha, wD.x); ffma2(acc0[7], ha, wD.y);
            ffma2(acc1[0], hb, wA.x); ffma2(acc1[1], hb, wA.y);
            ffma2(acc1[2], hb, wB.x); ffma2(acc1[3], hb, wB.y);
            ffma2(acc1[4], hb, wC.x); ffma2(acc1[5], hb, wC.y);
            ffma2(acc1[6], hb, wD.x); ffma2(acc1[7], hb, wD.y);
        }
#pragma unroll
        for (int q = 0; q < 4; q++) {
            int cb = cg * 16 + q * 4;
            float2 a0 = unpackf2(acc0[2*q]), a1 = unpackf2(acc0[2*q+1]);
            float2 b0 = unpackf2(acc1[2*q]), b1 = unpackf2(acc1[2*q+1]);
            float4 va = make_float4(a0.x, a0.y, a1.x, a1.y);
            float4 vb = make_float4(b0.x, b0.y, b1.x, b1.y);
            if (cb < 8 * FO) {
                Pv0[cb / 4] = va;
                if (v1) Pv1[cb / 4] = vb;
            } else if (cb < 9 * FO) {
                Rv0[(cb - 8 * FO) / 4] = va;
                if (v1) Rv1[(cb - 8 * FO) / 4] = vb;
            } else {
                int o = cb - 9 * FO;
                va.x += bsh[o]; va.y += bsh[o+1]; va.z += bsh[o+2]; va.w += bsh[o+3];
                vb.x += bsh[o]; vb.y += bsh[o+1]; vb.z += bsh[o+2]; vb.w += bsh[o+3];
                Av0[o / 4] = va;
                if (v1) Av1[o / 4] = vb;
            }
        }
    }
}

// ---------------- edge kernel ----------------
// Thread-per-edge over src-sorted edges. Consecutive threads share src -> P/R
// loads dedup in L1. msg = R[src] + sum_s e[s]*P[src,s,:]; red.v4 -> AGG[tgt].
template <int LAYER, int FO>
__global__ __launch_bounds__(256) void k_edge(const float4* __restrict__ e4)
{
    constexpr int FO4 = FO / 4;
    int i = blockIdx.x * 256 + threadIdx.x;
    if (i >= N_EDGES) return;

    int4 srt = g_srt[i];
    int src = srt.x, tgt = srt.y;
    float4 ea = e4[2 * srt.z];
    float4 eb = e4[2 * srt.z + 1];

    const float4* P = reinterpret_cast<const float4*>(g_P) + (size_t)src * (8 * FO4);
    const float4* R = reinterpret_cast<const float4*>(g_R) + (size_t)src * FO4;
    float* AGG;
    if (LAYER == 1)      AGG = g_AGG1;
    else if (LAYER == 2) AGG = g_AGG2;
    else                 AGG = g_AGG3;
    float* dstbase = AGG + (size_t)tgt * FO;

#pragma unroll
    for (int c = 0; c < FO4; c++) {
        float4 m = R[c];
        float4 p;
#define ACC_TERM(ES, SI) { p = P[(SI) * FO4 + c]; \
        m.x += (ES) * p.x; m.y += (ES) * p.y; m.z += (ES) * p.z; m.w += (ES) * p.w; }
        ACC_TERM(ea.x, 0) ACC_TERM(ea.y, 1) ACC_TERM(ea.z, 2) ACC_TERM(ea.w, 3)
        ACC_TERM(eb.x, 4) ACC_TERM(eb.y, 5) ACC_TERM(eb.z, 6) ACC_TERM(eb.w, 7)
#undef ACC_TERM
        asm volatile("red.global.add.v4.f32 [%0], {%1,%2,%3,%4};"
                     :: "l"(dstbase + c * 4), "f"(m.x), "f"(m.y), "f"(m.z), "f"(m.w));
    }
}

// ---------------- pool: partial[b][o] = sum over rows of relu(AGG3[n,o]) ----------------
__global__ void k_pool()  // 240 threads: t%24 = col, t/24 = row slot (10/block)
{
    __shared__ float sacc[24];
    int t = threadIdx.x;
    if (t < 24) sacc[t] = 0.0f;
    __syncthreads();
    int c = t % 24;
    int r0 = t / 24;
    float local = 0.0f;
    for (int r = blockIdx.x * 10 + r0; r < N_NODES; r += gridDim.x * 10) {
        local += fmaxf(g_AGG3[r * 24 + c], 0.0f);
    }
    atomicAdd(&sacc[c], local);
    __syncthreads();
    if (t < 24) g_poolpart[blockIdx.x * 24 + t] = sacc[t];
}

// ---------------- MLP ----------------
// a: pool-reduce + 24->96 relu + 96->256 relu (1 block, 256 threads)
__global__ void k_mlp_a(const float* __restrict__ W1, const float* __restrict__ b1,
                        const float* __restrict__ W2, const float* __restrict__ b2)
{
    __shared__ float v0[24];
    __shared__ float a1[96];
    int t = threadIdx.x;
    if (t < 24) {
        float s = 0.0f;
        for (int k = 0; k < 84; k++) s += g_poolpart[k * 24 + t];
        v0[t] = s;
    }
    __syncthreads();
    if (t < 96) {
        float acc = b1[t];
#pragma unroll
        for (int i = 0; i < 24; i++) acc += v0[i] * W1[i * 96 + t];
        a1[t] = fmaxf(acc, 0.0f);
    }
    __syncthreads();
    {
        float acc = b2[t];
#pragma unroll 8
        for (int i = 0; i < 96; i++) acc += a1[i] * W2[i * 256 + t];
        g_v1[t] = fmaxf(acc, 0.0f);
    }
}

// b: 256->768 relu (6 blocks x 128)
__global__ void k_mlp_b(const float* __restrict__ W3, const float* __restrict__ b3)
{
    __shared__ float in[256];
    int t = threadIdx.x;
    in[t] = g_v1[t];
    in[t + 128] = g_v1[t + 128];
    __syncthreads();
    int j = blockIdx.x * 128 + t;
    float acc = b3[j];
#pragma unroll 8
    for (int i = 0; i < 256; i++) acc += in[i] * W3[i * 768 + j];
    g_v2[j] = fmaxf(acc, 0.0f);
}

// c: 768->512 relu (4 blocks x 128)
__global__ void k_mlp_c(const float* __restrict__ W4, const float* __restrict__ b4)
{
    __shared__ float in[768];
    int t = threadIdx.x;
#pragma unroll
    for (int k = 0; k < 6; k++) in[t + k * 128] = g_v2[t + k * 128];
    __syncthreads();
    int j = blockIdx.x * 128 + t;
    float acc = b4[j];
#pragma unroll 8
    for (int i = 0; i < 768; i++) acc += in[i] * W4[i * 512 + j];
    g_v3[j] = fmaxf(acc, 0.0f);
}

// d: 512->64 relu + 64->1 (1 block, 64 threads)
__global__ void k_mlp_d(const float* __restrict__ W5, const float* __restrict__ b5,
                        const float* __restrict__ W6, const float* __restrict__ b6,
                        float* __restrict__ out)
{
    __shared__ float in[512];
    __shared__ float red[64];
    int t = threadIdx.x;
#pragma unroll
    for (int k = 0; k < 8; k++) in[t + k * 64] = g_v3[t + k * 64];
    __syncthreads();
    float acc = b5[t];
#pragma unroll 8
    for (int i = 0; i < 512; i++) acc += in[i] * W5[i * 64 + t];
    red[t] = fmaxf(acc, 0.0f) * W6[t];
    __syncthreads();
    if (t == 0) {
        float s = 0.0f;
#pragma unroll
        for (int i = 0; i < 64; i++) s += red[i];
        out[0] = s + b6[0];
    }
}

// ---------------- launcher ----------------
extern "C" void kernel_launch(void* const* d_in, const int* in_sizes, int n_in,
                              void* d_out, int out_size)
{
    const float* x    = (const float*)d_in[0];
    const int*   ei   = (const int*)d_in[1];
    const float* e    = (const float*)d_in[2];
    const float* We1  = (const float*)d_in[3];
    const float* be1  = (const float*)d_in[4];
    const float* root1= (const float*)d_in[5];
    const float* b1   = (const float*)d_in[6];
    const float* We2  = (const float*)d_in[7];
    const float* be2  = (const float*)d_in[8];
    const float* root2= (const float*)d_in[9];
    const float* b2   = (const float*)d_in[10];
    const float* We3  = (const float*)d_in[11];
    const float* be3  = (const float*)d_in[12];
    const float* root3= (const float*)d_in[13];
    const float* b3   = (const float*)d_in[14];
    const float* Wd1  = (const float*)d_in[15];
    const float* bd1  = (const float*)d_in[16];
    const float* Wd2  = (const float*)d_in[17];
    const float* bd2  = (const float*)d_in[18];
    const float* Wd3  = (const float*)d_in[19];
    const float* bd3  = (const float*)d_in[20];
    const float* Wd4  = (const float*)d_in[21];
    const float* bd4  = (const float*)d_in[22];
    const float* Wd5  = (const float*)d_in[23];
    const float* bd5  = (const float*)d_in[24];
    const float* Wd6  = (const float*)d_in[25];
    const float* bd6  = (const float*)d_in[26];

    const int2* ei2 = (const int2*)ei;
    const float4* e4 = (const float4*)e;

    // CSR build
    k_zero<<<(N_NODES + 255) / 256, 256>>>();
    k_hist<<<N_EDGES / 256, 256>>>(ei2);
    k_scan<<<1, 1024>>>();
    k_scatter<<<N_EDGES / 256, 256>>>(ei2);

    const int node_grid = (N_NODES + 255) / 256;   // 79 blocks x 128 thr x 2 nodes
    const int edge_grid = N_EDGES / 256;           // 625

    k_node<1, 16, 40><<<node_grid, 128>>>(x, We1, be1, root1, b1);
    k_edge<1, 40><<<edge_grid, 256>>>(e4);
    k_node<2, 40, 24><<<node_grid, 128>>>(nullptr, We2, be2, root2, b2);
    k_edge<2, 24><<<edge_grid, 256>>>(e4);
    k_node<3, 24, 24><<<node_grid, 128>>>(nullptr, We3, be3, root3, b3);
    k_edge<3, 24><<<edge_grid, 256>>>(e4);

    k_pool<<<84, 240>>>();
    k_mlp_a<<<1, 256>>>(Wd1, bd1, Wd2, bd2);
    k_mlp_b<<<6, 128>>>(Wd3, bd3);
    k_mlp_c<<<4, 128>>>(Wd4, bd4);
    k_mlp_d<<<1, 64>>>(Wd5, bd5, Wd6, bd6, (float*)d_out);
}

// round 3
// speedup vs baseline: 1.7066x; 1.4483x over previous
#include <cuda_runtime.h>
#include <cuda_bf16.h>

// ---------------- problem constants ----------------
#define N_NODES 20000
#define N_EDGES 160000

// ---------------- device scratch (static; no allocs) ----------------
__device__ __align__(16) float g_P[N_NODES * 320];   // P[n, s, o] (max 8*40 cols)
__device__ __align__(16) float g_R[N_NODES * 40];    // R[n, o]
__device__ __align__(16) float g_AGG1[N_NODES * 40];
__device__ __align__(16) float g_AGG2[N_NODES * 24];
__device__ __align__(16) float g_AGG3[N_NODES * 24];
__device__ int   g_deg[N_NODES];
__device__ int   g_cursor[N_NODES];
__device__ __align__(8)  int2   g_srt[N_EDGES];        // (src, tgt) sorted by src
__device__ __align__(16) float4 g_eperm[N_EDGES * 2];  // e payload, src-sorted
__device__ float g_poolpart[84 * 24];
__device__ __align__(16) float g_v1[256];
__device__ __align__(16) float g_v2[768];
__device__ __align__(16) float g_v3[512];

// ---------------- f32x2 helpers ----------------
__device__ __forceinline__ void ffma2(unsigned long long& d, unsigned long long a,
                                      unsigned long long b) {
    asm("fma.rn.f32x2 %0, %1, %2, %0;" : "+l"(d) : "l"(a), "l"(b));
}
__device__ __forceinline__ unsigned long long packf2(float x) {
    unsigned long long r;
    asm("mov.b64 %0, {%1, %1};" : "=l"(r) : "f"(x));
    return r;
}
__device__ __forceinline__ float2 unpackf2(unsigned long long v) {
    float2 f;
    asm("mov.b64 {%0, %1}, %2;" : "=f"(f.x), "=f"(f.y) : "l"(v));
    return f;
}

// ---------------- CSR build ----------------
__global__ void k_zero() {
    int i = blockIdx.x * blockDim.x + threadIdx.x;
    if (i < N_NODES) g_deg[i] = 0;
    if (i < 768) g_v2[i] = 0.0f;
    if (i < 512) g_v3[i] = 0.0f;
}

__global__ void k_hist(const int2* __restrict__ ei) {
    int i = blockIdx.x * blockDim.x + threadIdx.x;
    if (i < N_EDGES) atomicAdd(&g_deg[ei[i].x], 1);
}

__global__ void k_scan() {  // 1024 threads, shuffle-based scan over 20 items/thread
    __shared__ int wsum[32];
    int t = threadIdx.x;
    int lane = t & 31, wid = t >> 5;
    const int per = 20;
    int base = t * per;
    int deg[per];
    int s = 0;
#pragma unroll
    for (int i = 0; i < per; i++) {
        int idx = base + i;
        deg[i] = (idx < N_NODES) ? g_deg[idx] : 0;
        s += deg[i];
    }
    // warp inclusive scan
    int ws = s;
#pragma unroll
    for (int off = 1; off < 32; off <<= 1) {
        int n = __shfl_up_sync(0xffffffffu, ws, off);
        if (lane >= off) ws += n;
    }
    if (lane == 31) wsum[wid] = ws;
    __syncthreads();
    if (wid == 0) {
        int v = wsum[lane];
#pragma unroll
        for (int off = 1; off < 32; off <<= 1) {
            int n = __shfl_up_sync(0xffffffffu, v, off);
            if (lane >= off) v += n;
        }
        wsum[lane] = v;
    }
    __syncthreads();
    int wbase = (wid == 0) ? 0 : wsum[wid - 1];
    int run = wbase + ws - s;  // exclusive prefix for this thread
#pragma unroll
    for (int i = 0; i < per; i++) {
        int idx = base + i;
        if (idx < N_NODES) g_cursor[idx] = run;
        run += deg[i];
    }
}

__global__ void k_scatter(const int2* __restrict__ ei, const float4* __restrict__ e4) {
    int i = blockIdx.x * blockDim.x + threadIdx.x;
    if (i < N_EDGES) {
        int2 st = ei[i];
        int pos = atomicAdd(&g_cursor[st.x], 1);
        g_srt[pos] = st;
        g_eperm[2 * pos]     = e4[2 * i];
        g_eperm[2 * pos + 1] = e4[2 * i + 1];
    }
}

// ---------------- node kernel ----------------
// grid = (79 node-tiles, NCG/CC col-chunks); 256 threads, 1 node/thread.
// cols [0,8FO): P   cols [8FO,9FO): R   cols [9FO,10FO): AGG (+bias)
template <int LAYER, int FI, int FO, int CC>
__global__ __launch_bounds__(256) void k_node(
    const float* __restrict__ xin,
    const float* __restrict__ We, const float* __restrict__ be,
    const float* __restrict__ root, const float* __restrict__ bias)
{
    constexpr int COLS = 10 * FO;
    constexpr int CC16 = CC * 16;
    __shared__ __align__(16) float Wsh[FI * CC16];
    __shared__ float bsh[FO];
    int t = threadIdx.x;
    int cg0 = blockIdx.y * CC;
    int colbase = cg0 * 16;

    for (int idx = t; idx < FI * CC16; idx += 256) {
        int f = idx / CC16, cl = idx % CC16;
        int c = colbase + cl;
        float w;
        if (c < 8 * FO) {
            int s = c / FO, o = c % FO;
            w = We[s * (FI * FO) + f * FO + o];
        } else if (c < 9 * FO) {
            int o = c - 8 * FO;
            w = be[f * FO + o];
        } else {
            int o = c - 9 * FO;
            w = root[f * FO + o];
        }
        Wsh[idx] = w;
    }
    for (int idx = t; idx < FO; idx += 256) bsh[idx] = bias[idx];
    __syncthreads();

    int node = blockIdx.x * 256 + t;
    if (node >= N_NODES) return;

    const float* hin;
    if (LAYER == 1)      hin = xin;
    else if (LAYER == 2) hin = g_AGG1;
    else                 hin = g_AGG2;
    float* AGG;
    if (LAYER == 1)      AGG = g_AGG1;
    else if (LAYER == 2) AGG = g_AGG2;
    else                 AGG = g_AGG3;

    float h[FI];
    const float4* hv = reinterpret_cast<const float4*>(hin + (size_t)node * FI);
#pragma unroll
    for (int f4 = 0; f4 < FI / 4; f4++) {
        float4 a = hv[f4];
        if (LAYER != 1) {
            a.x = fmaxf(a.x, 0.f); a.y = fmaxf(a.y, 0.f);
            a.z = fmaxf(a.z, 0.f); a.w = fmaxf(a.w, 0.f);
        }
        h[4*f4+0]=a.x; h[4*f4+1]=a.y; h[4*f4+2]=a.z; h[4*f4+3]=a.w;
    }

    const ulonglong2* Wv = reinterpret_cast<const ulonglong2*>(Wsh);
    float4* Pv = reinterpret_cast<float4*>(g_P) + (size_t)node * (8 * FO / 4);
    float4* Rv = reinterpret_cast<float4*>(g_R) + (size_t)node * (FO / 4);
    float4* Av = reinterpret_cast<float4*>(AGG) + (size_t)node * (FO / 4);

#pragma unroll
    for (int cg = 0; cg < CC; cg++) {
        unsigned long long acc[8];
#pragma unroll
        for (int k = 0; k < 8; k++) acc[k] = 0ull;
#pragma unroll
        for (int f = 0; f < FI; f++) {
            const ulonglong2* wrow = Wv + f * (CC * 4) + cg * 4;
            ulonglong2 wA = wrow[0], wB = wrow[1], wC = wrow[2], wD = wrow[3];
            unsigned long long ha = packf2(h[f]);
            ffma2(acc[0], ha, wA.x); ffma2(acc[1], ha, wA.y);
            ffma2(acc[2], ha, wB.x); ffma2(acc[3], ha, wB.y);
            ffma2(acc[4], ha, wC.x); ffma2(acc[5], ha, wC.y);
            ffma2(acc[6], ha, wD.x); ffma2(acc[7], ha, wD.y);
        }
#pragma unroll
        for (int q = 0; q < 4; q++) {
            int cb = (cg0 + cg) * 16 + q * 4;
            float2 a0 = unpackf2(acc[2*q]), a1 = unpackf2(acc[2*q+1]);
            float4 va = make_float4(a0.x, a0.y, a1.x, a1.y);
            if (cb < 8 * FO) {
                Pv[cb / 4] = va;
            } else if (cb < 9 * FO) {
                Rv[(cb - 8 * FO) / 4] = va;
            } else {
                int o = cb - 9 * FO;
                va.x += bsh[o]; va.y += bsh[o+1]; va.z += bsh[o+2]; va.w += bsh[o+3];
                Av[o / 4] = va;
            }
        }
    }
}

// ---------------- edge kernel ----------------
// Thread-per-edge, src-sorted: P/R loads dedup in L1, e reads coalesced.
template <int LAYER, int FO>
__global__ __launch_bounds__(256) void k_edge()
{
    constexpr int FO4 = FO / 4;
    int i = blockIdx.x * 256 + threadIdx.x;
    if (i >= N_EDGES) return;

    int2 st = g_srt[i];
    int src = st.x, tgt = st.y;
    float4 ea = g_eperm[2 * i];
    float4 eb = g_eperm[2 * i + 1];

    const float4* P = reinterpret_cast<const float4*>(g_P) + (size_t)src * (8 * FO4);
    const float4* R = reinterpret_cast<const float4*>(g_R) + (size_t)src * FO4;
    float* AGG;
    if (LAYER == 1)      AGG = g_AGG1;
    else if (LAYER == 2) AGG = g_AGG2;
    else                 AGG = g_AGG3;
    float* dstbase = AGG + (size_t)tgt * FO;

#pragma unroll
    for (int c = 0; c < FO4; c++) {
        float4 m = R[c];
        float4 p;
#define ACC_TERM(ES, SI) { p = P[(SI) * FO4 + c]; \
        m.x += (ES) * p.x; m.y += (ES) * p.y; m.z += (ES) * p.z; m.w += (ES) * p.w; }
        ACC_TERM(ea.x, 0) ACC_TERM(ea.y, 1) ACC_TERM(ea.z, 2) ACC_TERM(ea.w, 3)
        ACC_TERM(eb.x, 4) ACC_TERM(eb.y, 5) ACC_TERM(eb.z, 6) ACC_TERM(eb.w, 7)
#undef ACC_TERM
        asm volatile("red.global.add.v4.f32 [%0], {%1,%2,%3,%4};"
                     :: "l"(dstbase + c * 4), "f"(m.x), "f"(m.y), "f"(m.z), "f"(m.w));
    }
}

// ---------------- pool ----------------
__global__ void k_pool()  // 240 threads: t%24 = col, t/24 = row slot
{
    __shared__ float sacc[24];
    int t = threadIdx.x;
    if (t < 24) sacc[t] = 0.0f;
    __syncthreads();
    int c = t % 24;
    int r0 = t / 24;
    float local = 0.0f;
    for (int r = blockIdx.x * 10 + r0; r < N_NODES; r += gridDim.x * 10) {
        local += fmaxf(g_AGG3[r * 24 + c], 0.0f);
    }
    atomicAdd(&sacc[c], local);
    __syncthreads();
    if (t < 24) g_poolpart[blockIdx.x * 24 + t] = sacc[t];
}

// ---------------- MLP ----------------
// a: pool-reduce + 24->96 relu + 96->256 relu  (1 block, 256 threads)
__global__ void k_mlp_a(const float* __restrict__ W1, const float* __restrict__ b1,
                        const float* __restrict__ W2, const float* __restrict__ b2)
{
    __shared__ float v0[24];
    __shared__ float a1[96];
    int t = threadIdx.x;
    if (t < 24) {
        float s = 0.0f;
        for (int k = 0; k < 84; k++) s += g_poolpart[k * 24 + t];
        v0[t] = s;
    }
    __syncthreads();
    if (t < 96) {
        float acc = b1[t];
#pragma unroll
        for (int i = 0; i < 24; i++) acc += v0[i] * W1[i * 96 + t];
        a1[t] = fmaxf(acc, 0.0f);
    }
    __syncthreads();
    {
        float acc = b2[t];
#pragma unroll 8
        for (int i = 0; i < 96; i++) acc += a1[i] * W2[i * 256 + t];
        g_v1[t] = fmaxf(acc, 0.0f);
    }
}

// b: 256->768, split-K atomics. grid (6 jtiles, 8 ksplits) x 128 thr. No relu here.
__global__ void k_mlp_b(const float* __restrict__ W3, const float* __restrict__ b3)
{
    __shared__ float in[32];
    int t = threadIdx.x;
    int k0 = blockIdx.y * 32;
    if (t < 32) in[t] = g_v1[k0 + t];
    __syncthreads();
    int j = blockIdx.x * 128 + t;
    float acc = (blockIdx.y == 0) ? b3[j] : 0.0f;
#pragma unroll 8
    for (int i = 0; i < 32; i++) acc += in[i] * W3[(k0 + i) * 768 + j];
    atomicAdd(&g_v2[j], acc);
}

// c: 768->512, split-K atomics. grid (4 jtiles, 16 ksplits) x 128 thr. relu applied on read.
__global__ void k_mlp_c(const float* __restrict__ W4, const float* __restrict__ b4)
{
    __shared__ float in[48];
    int t = threadIdx.x;
    int k0 = blockIdx.y * 48;
    if (t < 48) in[t] = fmaxf(g_v2[k0 + t], 0.0f);
    __syncthreads();
    int j = blockIdx.x * 128 + t;
    float acc = (blockIdx.y == 0) ? b4[j] : 0.0f;
#pragma unroll 8
    for (int i = 0; i < 48; i++) acc += in[i] * W4[(k0 + i) * 512 + j];
    atomicAdd(&g_v3[j], acc);
}

// d: 512->64 relu + 64->1  (1 block, 512 threads)
__global__ void k_mlp_d(const float* __restrict__ W5, const float* __restrict__ b5,
                        const float* __restrict__ W6, const float* __restrict__ b6,
                        float* __restrict__ out)
{
    __shared__ float in[512];
    __shared__ float sacc[64];
    __shared__ float red[64];
    int t = threadIdx.x;
    in[t] = fmaxf(g_v3[t], 0.0f);
    if (t < 64) sacc[t] = b5[t];
    __syncthreads();
    int j = t & 63;
    int k0 = (t >> 6) * 64;
    float acc = 0.0f;
#pragma unroll 8
    for (int i = 0; i < 64; i++) acc += in[k0 + i] * W5[(k0 + i) * 64 + j];
    atomicAdd(&sacc[j], acc);
    __syncthreads();
    if (t < 64) red[t] = fmaxf(sacc[t], 0.0f) * W6[t];
    __syncthreads();
    if (t == 0) {
        float s = 0.0f;
#pragma unroll
        for (int i = 0; i < 64; i++) s += red[i];
        out[0] = s + b6[0];
    }
}

// ---------------- launcher ----------------
extern "C" void kernel_launch(void* const* d_in, const int* in_sizes, int n_in,
                              void* d_out, int out_size)
{
    const float* x    = (const float*)d_in[0];
    const int*   ei   = (const int*)d_in[1];
    const float* e    = (const float*)d_in[2];
    const float* We1  = (const float*)d_in[3];
    const float* be1  = (const float*)d_in[4];
    const float* root1= (const float*)d_in[5];
    const float* b1   = (const float*)d_in[6];
    const float* We2  = (const float*)d_in[7];
    const float* be2  = (const float*)d_in[8];
    const float* root2= (const float*)d_in[9];
    const float* b2   = (const float*)d_in[10];
    const float* We3  = (const float*)d_in[11];
    const float* be3  = (const float*)d_in[12];
    const float* root3= (const float*)d_in[13];
    const float* b3   = (const float*)d_in[14];
    const float* Wd1  = (const float*)d_in[15];
    const float* bd1  = (const float*)d_in[16];
    const float* Wd2  = (const float*)d_in[17];
    const float* bd2  = (const float*)d_in[18];
    const float* Wd3  = (const float*)d_in[19];
    const float* bd3  = (const float*)d_in[20];
    const float* Wd4  = (const float*)d_in[21];
    const float* bd4  = (const float*)d_in[22];
    const float* Wd5  = (const float*)d_in[23];
    const float* bd5  = (const float*)d_in[24];
    const float* Wd6  = (const float*)d_in[25];
    const float* bd6  = (const float*)d_in[26];

    const int2* ei2 = (const int2*)ei;
    const float4* e4 = (const float4*)e;

    // CSR build
    k_zero<<<(N_NODES + 255) / 256, 256>>>();
    k_hist<<<N_EDGES / 256, 256>>>(ei2);
    k_scan<<<1, 1024>>>();
    k_scatter<<<N_EDGES / 256, 256>>>(ei2, e4);

    const int ntile = (N_NODES + 255) / 256;       // 79
    const int edge_grid = N_EDGES / 256;           // 625

    k_node<1, 16, 40, 5><<<dim3(ntile, 5), 256>>>(x, We1, be1, root1, b1);
    k_edge<1, 40><<<edge_grid, 256>>>();
    k_node<2, 40, 24, 5><<<dim3(ntile, 3), 256>>>(nullptr, We2, be2, root2, b2);
    k_edge<2, 24><<<edge_grid, 256>>>();
    k_node<3, 24, 24, 5><<<dim3(ntile, 3), 256>>>(nullptr, We3, be3, root3, b3);
    k_edge<3, 24><<<edge_grid, 256>>>();

    k_pool<<<84, 240>>>();
    k_mlp_a<<<1, 256>>>(Wd1, bd1, Wd2, bd2);
    k_mlp_b<<<dim3(6, 8), 128>>>(Wd3, bd3);
    k_mlp_c<<<dim3(4, 16), 128>>>(Wd4, bd4);
    k_mlp_d<<<1, 512>>>(Wd5, bd5, Wd6, bd6, (float*)d_out);
}